// round 13
// baseline (speedup 1.0000x reference)
#include <cuda_runtime.h>
#include <cuda_fp16.h>
#include <math.h>
#include <stdint.h>

// Problem constants
#define NN      50000
#define NE      800000
#define ND      128
#define ED      32
#define CATD    288
#define KPAD    288     // divisible by KC=32
#define GD      384     // 3*ND
#define NROUNDS 2

#define SCAN_BLK 1024
#define NSCANBLK ((NN + SCAN_BLK - 1) / SCAN_BLK)   // 49

// ---------------- device scratch -------------------------------------------
__device__ int   g_cnt[NN];
__device__ int   g_rowptr[NN + 1];
__device__ int   g_cursor[NN];
__device__ float g_degf[NN];
__device__ int   g_bsum[64];
__device__ int   g_boffs[64];
__device__ int   g_eidx[NE];
__device__ float g_E[(size_t)NN * ED];          // per-node edge-feature sum (round-invariant)

__device__ __half g_Xh[(size_t)NN * KPAD];      // A-split hi of X
__device__ __half g_Xl[(size_t)NN * KPAD];      // A-split lo of X
// cat = [a (cols 0-127) | H (cols 128-255)] fp16 hi/lo
__device__ __half g_cath[(size_t)NN * 256];
__device__ __half g_catl[(size_t)NN * 256];
__device__ float g_grz[(size_t)NN * 256];
__device__ float g_in[(size_t)NN * ND];
__device__ float g_hn[(size_t)NN * ND];

// weights (per round, rebuilt) — single fp16 (B-side rounding ~2^-12 only)
__device__ __half g_Bmsg[ND * KPAD];
__device__ __half g_Brz[256 * 256];   // stacked [Wih;Whh] r,z gates, transposed
__device__ __half g_Bin[ND * ND];     // Wih_n transposed
__device__ __half g_Bwn[ND * ND];     // Whh_n transposed
__device__ float g_brz[256];          // b_ih + b_hh (r,z gates)

// ---------------- small helpers --------------------------------------------
__device__ __forceinline__ void split2h(float x, __half& h, __half& l) {
    h = __float2half_rn(x);
    l = __float2half_rn(x - __half2float(h));
}

__device__ __forceinline__ uint32_t smem_u32(const void* p) {
    uint32_t a;
    asm("{ .reg .u64 t; cvta.to.shared.u64 t, %1; cvt.u32.u64 %0, t; }" : "=r"(a) : "l"(p));
    return a;
}

__device__ __forceinline__ void ldm_x4(uint32_t* r, uint32_t addr) {
    asm volatile("ldmatrix.sync.aligned.m8n8.x4.shared.b16 {%0,%1,%2,%3}, [%4];"
        : "=r"(r[0]), "=r"(r[1]), "=r"(r[2]), "=r"(r[3]) : "r"(addr));
}

__device__ __forceinline__ void mma_f16(float* c, const uint32_t* a, const uint32_t* b) {
    asm volatile(
        "mma.sync.aligned.m16n8k16.row.col.f32.f16.f16.f32 "
        "{%0,%1,%2,%3}, {%4,%5,%6,%7}, {%8,%9}, {%0,%1,%2,%3};"
        : "+f"(c[0]), "+f"(c[1]), "+f"(c[2]), "+f"(c[3])
        : "r"(a[0]), "r"(a[1]), "r"(a[2]), "r"(a[3]), "r"(b[0]), "r"(b[1]));
}

__device__ __forceinline__ void cpasync16(uint32_t saddr, const void* gptr) {
    asm volatile("cp.async.cg.shared.global [%0], [%1], 16;"
                 :: "r"(saddr), "l"(gptr));
}

// ---------------- init / CSR kernels ----------------------------------------
__global__ void copy_split_kernel(const float* __restrict__ src, float* __restrict__ dst,
                                  int n) {
    int i = blockIdx.x * blockDim.x + threadIdx.x;
    if (i < n) {
        float v = src[i];
        dst[i] = v;
        int vv = i / ND, j = i - vv * ND;
        split2h(v, g_cath[(size_t)vv * 256 + 128 + j], g_catl[(size_t)vv * 256 + 128 + j]);
    }
}

__global__ void zero_cnt() {
    int i = blockIdx.x * blockDim.x + threadIdx.x;
    if (i < NN) g_cnt[i] = 0;
}

__global__ void count_kernel(const int* __restrict__ dst) {
    int e = blockIdx.x * blockDim.x + threadIdx.x;
    if (e < NE) atomicAdd(&g_cnt[dst[e]], 1);
}

__global__ void scan1() {
    __shared__ int buf[SCAN_BLK];
    int tid = threadIdx.x;
    int i = blockIdx.x * SCAN_BLK + tid;
    buf[tid] = (i < NN) ? g_cnt[i] : 0;
    __syncthreads();
    #pragma unroll
    for (int off = 1; off < SCAN_BLK; off <<= 1) {
        int t = (tid >= off) ? buf[tid - off] : 0;
        __syncthreads();
        buf[tid] += t;
        __syncthreads();
    }
    if (i < NN) g_rowptr[1 + i] = buf[tid];
    if (tid == SCAN_BLK - 1) g_bsum[blockIdx.x] = buf[tid];
}

__global__ void scan2() {
    __shared__ int buf[64];
    int tid = threadIdx.x;
    int own = (tid < NSCANBLK) ? g_bsum[tid] : 0;
    buf[tid] = own;
    __syncthreads();
    #pragma unroll
    for (int off = 1; off < 64; off <<= 1) {
        int t = (tid >= off) ? buf[tid - off] : 0;
        __syncthreads();
        buf[tid] += t;
        __syncthreads();
    }
    if (tid < NSCANBLK) g_boffs[tid] = buf[tid] - own;
}

__global__ void scan3() {
    int i = blockIdx.x * blockDim.x + threadIdx.x;
    if (i >= NN) return;
    int b = i / SCAN_BLK;
    int incl = g_rowptr[1 + i] + g_boffs[b];
    g_rowptr[1 + i] = incl;
    int c = g_cnt[i];
    g_cursor[i] = incl - c;
    g_degf[i]   = (float)c;
    if (i == 0) g_rowptr[0] = 0;
}

__global__ void fill_kernel(const int* __restrict__ dst) {
    int e = blockIdx.x * blockDim.x + threadIdx.x;
    if (e < NE) {
        int d = dst[e];
        int p = atomicAdd(&g_cursor[d], 1);
        g_eidx[p] = e;
    }
}

// per-node edge-feature sum (once; invariant across rounds)
__global__ void esum_kernel(const float* __restrict__ he) {
    int warp = (blockIdx.x * blockDim.x + threadIdx.x) >> 5;
    int lane = threadIdx.x & 31;
    if (warp >= NN) return;
    int beg = g_rowptr[warp], end = g_rowptr[warp + 1];
    float se = 0.f;
    for (int i = beg; i < end; i++)
        se += he[(size_t)g_eidx[i] * ED + lane];
    g_E[(size_t)warp * ED + lane] = se;
}

// ---------------- weight transpose (single fp16) -----------------------------
__global__ void conv_wmsg(const float* __restrict__ W) {
    int idx = blockIdx.x * blockDim.x + threadIdx.x;
    if (idx >= ND * KPAD) return;
    int n = idx / KPAD;
    int k = idx - n * KPAD;
    g_Bmsg[idx] = __float2half_rn(W[(size_t)k * ND + n]);
}

// r,z gate weights: [256 n][256 k] (k<128 -> Wih, k>=128 -> Whh), + summed bias
__global__ void conv_rz(const float* __restrict__ Wih, const float* __restrict__ Whh,
                        const float* __restrict__ bih, const float* __restrict__ bhh) {
    int idx = blockIdx.x * blockDim.x + threadIdx.x;
    if (idx >= 256 * 256) return;
    int n = idx >> 8;
    int k = idx & 255;
    float v = (k < 128) ? Wih[(size_t)k * GD + n] : Whh[(size_t)(k - 128) * GD + n];
    g_Brz[idx] = __float2half_rn(v);
    if (idx < 256) g_brz[idx] = bih[idx] + bhh[idx];
}

// n-gate weights: Bin = Wih_n^T, Bwn = Whh_n^T  (each [128 n][128 k])
__global__ void conv_n(const float* __restrict__ Wih, const float* __restrict__ Whh) {
    int idx = blockIdx.x * blockDim.x + threadIdx.x;
    if (idx >= 2 * ND * ND) return;
    int which = idx >> 14;          // 0 -> Bin, 1 -> Bwn
    int r = idx & (ND * ND - 1);
    int n = r >> 7;
    int k = r & 127;
    if (which == 0)
        g_Bin[r] = __float2half_rn(Wih[(size_t)k * GD + 256 + n]);
    else
        g_Bwn[r] = __float2half_rn(Whh[(size_t)k * GD + 256 + n]);
}

// ---------------- gather: X = [S | deg*hv | E] as fp16 splits ----------------
// float4 row loads: lane l covers features 4l..4l+3. Per-feature accumulation
// order over edges is IDENTICAL to the scalar version (bit-exact X).
__global__ void gather_kernel(const float* __restrict__ hv, const int* __restrict__ src) {
    int warp = (blockIdx.x * blockDim.x + threadIdx.x) >> 5;
    int lane = threadIdx.x & 31;
    if (warp >= NN) return;
    int v = warp;
    int beg = g_rowptr[v];
    int end = g_rowptr[v + 1];
    float s0 = 0.f, s1 = 0.f, s2 = 0.f, s3 = 0.f;
    const float4* hv4 = (const float4*)hv;
    for (int i = beg; i < end; i++) {
        int e = g_eidx[i];
        int s = src[e];
        float4 r = hv4[(size_t)s * (ND / 4) + lane];
        s0 += r.x; s1 += r.y; s2 += r.z; s3 += r.w;
    }
    float d = g_degf[v];
    float4 hr = hv4[(size_t)v * (ND / 4) + lane];
    __half* xh = g_Xh + (size_t)v * KPAD;
    __half* xl = g_Xl + (size_t)v * KPAD;
    float vals[9];
    vals[0] = s0; vals[1] = s1; vals[2] = s2; vals[3] = s3;
    vals[4] = d * hr.x;
    vals[5] = d * hr.y;
    vals[6] = d * hr.z;
    vals[7] = d * hr.w;
    vals[8] = g_E[(size_t)v * ED + lane];
    // features: S -> xh[4*lane + q], deg*hv -> xh[128 + 4*lane + q], E -> xh[256+lane]
    #pragma unroll
    for (int q = 0; q < 4; q++)
        split2h(vals[q], xh[4 * lane + q], xl[4 * lane + q]);
    #pragma unroll
    for (int q = 0; q < 4; q++)
        split2h(vals[4 + q], xh[128 + 4 * lane + q], xl[128 + 4 * lane + q]);
    split2h(vals[8], xh[256 + lane], xl[256 + lane]);
}

// ---------------- cp.async 4-stage HMMA fp16 A-split GEMM body ---------------
// C[M, ...] = (Ah+Al)[M,K] @ B^T  (B stored [Ncols][K], K-major fp16)
//   + rowscale*bias.  128x128 CTA tile, 8 warps, K chunk 32, 4 smem stages.
// 2 MMA passes: Ah@B + Al@B, fp32 accumulate (bit-identical to 3-stage version).
#define KC 32
#define STG_BYTES 24576   // 3 tiles (Ah, Al, B) x 8KB per stage
#define NSTG 4
#define SMG_BIAS  0
#define SMG_STAGE 1024
#define SMG_TOTAL (1024 + NSTG * STG_BYTES)   // 99328 -> 2 CTAs/SM

__device__ __forceinline__
void gemm_body(const __half* __restrict__ Ah, const __half* __restrict__ Al,
               int lda,
               const __half* __restrict__ B, int ldb,
               const float* __restrict__ bias, const float* __restrict__ rowscale,
               float* __restrict__ Cf, int ldcf,
               __half* __restrict__ Chi, __half* __restrict__ Clo, int ldch,
               int M, int K, int blockRow, int blockCol, char* smem) {
    int tid = threadIdx.x, wid = tid >> 5, lane = tid & 31;
    int warpRow = (wid >> 2) * 64;   // 0 / 64
    int warpCol = (wid & 3) * 32;    // 0..96

    float* sBias = (float*)(smem + SMG_BIAS);
    if (tid < 128) sBias[tid] = bias[blockCol + tid];

    uint32_t sstage = smem_u32(smem + SMG_STAGE);

    float acc[4][4][4];
    #pragma unroll
    for (int mt = 0; mt < 4; mt++)
        #pragma unroll
        for (int nt = 0; nt < 4; nt++)
            #pragma unroll
            for (int q = 0; q < 4; q++) acc[mt][nt][q] = 0.f;

    // per-thread load mapping: 2 x 16B vecs per tile (128 rows x 64B rows)
    int l0 = tid, l1 = 256 + tid;
    int r0l = l0 >> 2, c0 = (l0 & 3) * 16;
    int r1l = l1 >> 2, c1 = (l1 & 3) * 16;
    int sw0 = (r0l * 64 + c0) ^ (((r0l * 64 + c0) >> 3) & 0x30);
    int sw1 = (r1l * 64 + c1) ^ (((r1l * 64 + c1) >> 3) & 0x30);
    int ga0 = blockRow + r0l; if (ga0 >= M) ga0 = M - 1;
    int ga1 = blockRow + r1l; if (ga1 >= M) ga1 = M - 1;
    int gb0 = blockCol + r0l;
    int gb1 = blockCol + r1l;

    int nchunks = K / KC;

    // prologue: prefetch chunks 0..2 (nchunks >= 4 for all our calls)
    #pragma unroll
    for (int p = 0; p < 3; p++) {
        int k0 = p * KC;
        uint32_t st = sstage + p * STG_BYTES;
        cpasync16(st + sw0,          (const char*)(Ah + (size_t)ga0 * lda + k0) + c0);
        cpasync16(st + sw1,          (const char*)(Ah + (size_t)ga1 * lda + k0) + c1);
        cpasync16(st + 8192 + sw0,   (const char*)(Al + (size_t)ga0 * lda + k0) + c0);
        cpasync16(st + 8192 + sw1,   (const char*)(Al + (size_t)ga1 * lda + k0) + c1);
        cpasync16(st + 16384 + sw0,  (const char*)(B + (size_t)gb0 * ldb + k0) + c0);
        cpasync16(st + 16384 + sw1,  (const char*)(B + (size_t)gb1 * ldb + k0) + c1);
        asm volatile("cp.async.commit_group;" ::: "memory");
    }

    int lrow  = lane & 15;
    uint32_t lhalf = (uint32_t)((lane >> 4) * 16);
    uint32_t rm = (uint32_t)(((lrow >> 1) & 3) << 4);

    int stage = 0;
    for (int kc = 0; kc < nchunks; kc++) {
        // wait for chunk kc (2 newer groups may still fly), sync all warps
        asm volatile("cp.async.wait_group 2;" ::: "memory");
        __syncthreads();

        // prefetch chunk kc+3 into stage (kc+3)%4 — that stage held chunk kc-1,
        // whose compute finished before the sync above.
        if (kc + 3 < nchunks) {
            int k0 = (kc + 3) * KC;
            int s3 = stage + 3; if (s3 >= NSTG) s3 -= NSTG;
            uint32_t st = sstage + s3 * STG_BYTES;
            cpasync16(st + sw0,          (const char*)(Ah + (size_t)ga0 * lda + k0) + c0);
            cpasync16(st + sw1,          (const char*)(Ah + (size_t)ga1 * lda + k0) + c1);
            cpasync16(st + 8192 + sw0,   (const char*)(Al + (size_t)ga0 * lda + k0) + c0);
            cpasync16(st + 8192 + sw1,   (const char*)(Al + (size_t)ga1 * lda + k0) + c1);
            cpasync16(st + 16384 + sw0,  (const char*)(B + (size_t)gb0 * ldb + k0) + c0);
            cpasync16(st + 16384 + sw1,  (const char*)(B + (size_t)gb1 * ldb + k0) + c1);
        }
        asm volatile("cp.async.commit_group;" ::: "memory");

        uint32_t stb = sstage + stage * STG_BYTES;
        uint32_t sAH = stb, sAL = stb + 8192, sB = stb + 16384;

        #pragma unroll
        for (int ks = 0; ks < 2; ks++) {
            uint32_t koff = ((uint32_t)(ks * 32) + lhalf) ^ rm;
            uint32_t bf[4][2];
            #pragma unroll
            for (int ng = 0; ng < 2; ng++) {
                uint32_t ro = (uint32_t)(warpCol + ng * 16 + lrow) * 64 + koff;
                uint32_t t[4];
                ldm_x4(t, sB + ro);
                bf[ng * 2 + 0][0] = t[0]; bf[ng * 2 + 1][0] = t[1];
                bf[ng * 2 + 0][1] = t[2]; bf[ng * 2 + 1][1] = t[3];
            }
            #pragma unroll
            for (int mt = 0; mt < 4; mt++) {
                uint32_t ro = (uint32_t)(warpRow + mt * 16 + lrow) * 64 + koff;
                uint32_t ah[4], al[4];
                ldm_x4(ah, sAH + ro);
                ldm_x4(al, sAL + ro);
                #pragma unroll
                for (int nt = 0; nt < 4; nt++) {
                    mma_f16(acc[mt][nt], ah, bf[nt]);
                    mma_f16(acc[mt][nt], al, bf[nt]);
                }
            }
        }
        stage++; if (stage >= NSTG) stage = 0;
    }

    // ---- epilogue ----
    int rbase = blockRow + warpRow;
    #pragma unroll
    for (int mt = 0; mt < 4; mt++) {
        int r0 = rbase + mt * 16 + (lane >> 2);
        int r1 = r0 + 8;
        float rs0 = 1.f, rs1 = 1.f;
        if (rowscale) {
            if (r0 < M) rs0 = rowscale[r0];
            if (r1 < M) rs1 = rowscale[r1];
        }
        #pragma unroll
        for (int nt = 0; nt < 4; nt++) {
            int col = warpCol + nt * 8 + (lane & 3) * 2;
            float b0 = sBias[col], b1 = sBias[col + 1];
            int gcol = blockCol + col;
            float v00 = acc[mt][nt][0] + rs0 * b0;
            float v01 = acc[mt][nt][1] + rs0 * b1;
            float v10 = acc[mt][nt][2] + rs1 * b0;
            float v11 = acc[mt][nt][3] + rs1 * b1;
            if (Cf) {
                if (r0 < M) *(float2*)(Cf + (size_t)r0 * ldcf + gcol) = make_float2(v00, v01);
                if (r1 < M) *(float2*)(Cf + (size_t)r1 * ldcf + gcol) = make_float2(v10, v11);
            }
            if (Chi) {
                __half h0, l0x, h1, l1;
                if (r0 < M) {
                    split2h(v00, h0, l0x); split2h(v01, h1, l1);
                    *(unsigned*)(Chi + (size_t)r0 * ldch + gcol) =
                        ((unsigned)__half_as_ushort(h1) << 16) | __half_as_ushort(h0);
                    *(unsigned*)(Clo + (size_t)r0 * ldch + gcol) =
                        ((unsigned)__half_as_ushort(l1) << 16) | __half_as_ushort(l0x);
                }
                if (r1 < M) {
                    split2h(v10, h0, l0x); split2h(v11, h1, l1);
                    *(unsigned*)(Chi + (size_t)r1 * ldch + gcol) =
                        ((unsigned)__half_as_ushort(h1) << 16) | __half_as_ushort(h0);
                    *(unsigned*)(Clo + (size_t)r1 * ldch + gcol) =
                        ((unsigned)__half_as_ushort(l1) << 16) | __half_as_ushort(l0x);
                }
            }
        }
    }
}

// msg GEMM: a = X @ Wmsg + deg*b_msg -> cat cols 0-127 (fp16 splits)
__global__ __launch_bounds__(256, 2)
void gemm_msg(const float* __restrict__ bmsg) {
    extern __shared__ char smem[];
    gemm_body(g_Xh, g_Xl, KPAD, g_Bmsg, KPAD,
              bmsg, g_degf,
              (float*)nullptr, 0, g_cath, g_catl, 256,
              NN, KPAD, blockIdx.y * 128, 0, smem);
}

// merged gate GEMMs: x=0,1 -> grz cols; x=2 -> in_ = a@Wih_n; x=3 -> hn = H@Whh_n
__global__ __launch_bounds__(256, 2)
void gemm_gates(const float* __restrict__ bihn, const float* __restrict__ bhhn) {
    extern __shared__ char smem[];
    int bx = blockIdx.x;
    if (bx < 2) {
        gemm_body(g_cath, g_catl, 256, g_Brz, 256,
                  g_brz, (const float*)nullptr,
                  g_grz, 256, (__half*)nullptr, (__half*)nullptr, 0,
                  NN, 256, blockIdx.y * 128, bx * 128, smem);
    } else if (bx == 2) {
        gemm_body(g_cath, g_catl, 256, g_Bin, ND,
                  bihn, (const float*)nullptr,
                  g_in, ND, (__half*)nullptr, (__half*)nullptr, 0,
                  NN, ND, blockIdx.y * 128, 0, smem);
    } else {
        gemm_body(g_cath + 128, g_catl + 128, 256, g_Bwn, ND,
                  bhhn, (const float*)nullptr,
                  g_hn, ND, (__half*)nullptr, (__half*)nullptr, 0,
                  NN, ND, blockIdx.y * 128, 0, smem);
    }
}

// ---------------- GRU elementwise --------------------------------------------
__global__ void gru_kernel(float* __restrict__ hv) {
    int idx = blockIdx.x * blockDim.x + threadIdx.x;
    if (idx >= NN * ND) return;
    int v = idx / ND;
    int j = idx - v * ND;
    float grv = g_grz[(size_t)v * 256 + j];
    float gzv = g_grz[(size_t)v * 256 + 128 + j];
    float inv = g_in[(size_t)v * ND + j];
    float hnv = g_hn[(size_t)v * ND + j];
    float r = 1.0f / (1.0f + expf(-grv));
    float z = 1.0f / (1.0f + expf(-gzv));
    float n = tanhf(inv + r * hnv);
    float h = hv[idx];
    float o = (1.0f - z) * n + z * h;
    hv[idx] = o;
    split2h(o, g_cath[(size_t)v * 256 + 128 + j], g_catl[(size_t)v * 256 + 128 + j]);
}

// ---------------- launch -----------------------------------------------------
extern "C" void kernel_launch(void* const* d_in, const int* in_sizes, int n_in,
                              void* d_out, int out_size) {
    const float* hv    = (const float*)d_in[0];
    const float* he    = (const float*)d_in[1];
    const int*   src   = (const int*)d_in[2];
    const int*   dst   = (const int*)d_in[3];
    const float* W_msg = (const float*)d_in[4];
    const float* b_msg = (const float*)d_in[5];
    const float* W_ih  = (const float*)d_in[6];
    const float* W_hh  = (const float*)d_in[7];
    const float* b_ih  = (const float*)d_in[8];
    const float* b_hh  = (const float*)d_in[9];
    float* H = (float*)d_out;

    static int attr_done = 0;
    if (!attr_done) {
        cudaFuncSetAttribute(gemm_msg,   cudaFuncAttributeMaxDynamicSharedMemorySize, SMG_TOTAL);
        cudaFuncSetAttribute(gemm_gates, cudaFuncAttributeMaxDynamicSharedMemorySize, SMG_TOTAL);
        attr_done = 1;
    }

    copy_split_kernel<<<(NN * ND + 255) / 256, 256>>>(hv, H, NN * ND);
    zero_cnt<<<(NN + 255) / 256, 256>>>();
    count_kernel<<<(NE + 255) / 256, 256>>>(dst);
    scan1<<<NSCANBLK, SCAN_BLK>>>();
    scan2<<<1, 64>>>();
    scan3<<<(NN + 255) / 256, 256>>>();
    fill_kernel<<<(NE + 255) / 256, 256>>>(dst);
    esum_kernel<<<(NN * 32 + 255) / 256, 256>>>(he);

    int mtiles = (NN + 127) / 128;   // 391

    for (int t = 0; t < NROUNDS; t++) {
        conv_wmsg<<<(ND * KPAD + 255) / 256, 256>>>(W_msg + (size_t)t * CATD * ND);
        conv_rz<<<(256 * 256 + 255) / 256, 256>>>(W_ih + (size_t)t * ND * GD,
                                                  W_hh + (size_t)t * ND * GD,
                                                  b_ih + (size_t)t * GD,
                                                  b_hh + (size_t)t * GD);
        conv_n<<<(2 * ND * ND + 255) / 256, 256>>>(W_ih + (size_t)t * ND * GD,
                                                   W_hh + (size_t)t * ND * GD);

        gather_kernel<<<(NN * 32 + 255) / 256, 256>>>(H, src);

        gemm_msg<<<dim3(1, mtiles), 256, SMG_TOTAL>>>(b_msg + (size_t)t * ND);
        gemm_gates<<<dim3(4, mtiles), 256, SMG_TOTAL>>>(b_ih + (size_t)t * GD + 256,
                                                        b_hh + (size_t)t * GD + 256);

        gru_kernel<<<(NN * ND + 255) / 256, 256>>>(H);
    }
}

// round 14
// speedup vs baseline: 1.0211x; 1.0211x over previous
#include <cuda_runtime.h>
#include <cuda_fp16.h>
#include <math.h>
#include <stdint.h>

// Problem constants
#define NN      50000
#define NE      800000
#define ND      128
#define ED      32
#define CATD    288
#define KPAD    288     // divisible by KC=32
#define GD      384     // 3*ND
#define NROUNDS 2

#define SCAN_BLK 1024
#define NSCANBLK ((NN + SCAN_BLK - 1) / SCAN_BLK)   // 49

// ---------------- device scratch -------------------------------------------
__device__ int   g_cnt[NN];
__device__ int   g_rowptr[NN + 1];
__device__ int   g_cursor[NN];
__device__ float g_degf[NN];
__device__ int   g_bsum[64];
__device__ int   g_boffs[64];
__device__ int   g_eidx[NE];
__device__ float g_E[(size_t)NN * ED];          // per-node edge-feature sum (round-invariant)

__device__ __half g_Xh[(size_t)NN * KPAD];      // A-split hi of X
__device__ __half g_Xl[(size_t)NN * KPAD];      // A-split lo of X
// cat = [a (cols 0-127) | H (cols 128-255)] fp16 hi/lo
__device__ __half g_cath[(size_t)NN * 256];
__device__ __half g_catl[(size_t)NN * 256];
__device__ float g_grz[(size_t)NN * 256];
__device__ float g_in[(size_t)NN * ND];
__device__ float g_hn[(size_t)NN * ND];

// weights (per round, rebuilt) — single fp16 (B-side rounding ~2^-12 only)
__device__ __half g_Bmsg[ND * KPAD];
__device__ __half g_Brz[256 * 256];   // stacked [Wih;Whh] r,z gates, transposed
__device__ __half g_Bin[ND * ND];     // Wih_n transposed
__device__ __half g_Bwn[ND * ND];     // Whh_n transposed
__device__ float g_brz[256];          // b_ih + b_hh (r,z gates)

// ---------------- small helpers --------------------------------------------
__device__ __forceinline__ void split2h(float x, __half& h, __half& l) {
    h = __float2half_rn(x);
    l = __float2half_rn(x - __half2float(h));
}

__device__ __forceinline__ uint32_t smem_u32(const void* p) {
    uint32_t a;
    asm("{ .reg .u64 t; cvta.to.shared.u64 t, %1; cvt.u32.u64 %0, t; }" : "=r"(a) : "l"(p));
    return a;
}

__device__ __forceinline__ void ldm_x4(uint32_t* r, uint32_t addr) {
    asm volatile("ldmatrix.sync.aligned.m8n8.x4.shared.b16 {%0,%1,%2,%3}, [%4];"
        : "=r"(r[0]), "=r"(r[1]), "=r"(r[2]), "=r"(r[3]) : "r"(addr));
}

__device__ __forceinline__ void mma_f16(float* c, const uint32_t* a, const uint32_t* b) {
    asm volatile(
        "mma.sync.aligned.m16n8k16.row.col.f32.f16.f16.f32 "
        "{%0,%1,%2,%3}, {%4,%5,%6,%7}, {%8,%9}, {%0,%1,%2,%3};"
        : "+f"(c[0]), "+f"(c[1]), "+f"(c[2]), "+f"(c[3])
        : "r"(a[0]), "r"(a[1]), "r"(a[2]), "r"(a[3]), "r"(b[0]), "r"(b[1]));
}

__device__ __forceinline__ void cpasync16(uint32_t saddr, const void* gptr) {
    asm volatile("cp.async.cg.shared.global [%0], [%1], 16;"
                 :: "r"(saddr), "l"(gptr));
}

// ---------------- init / CSR kernels ----------------------------------------
__global__ void copy_split_kernel(const float* __restrict__ src, float* __restrict__ dst,
                                  int n) {
    int i = blockIdx.x * blockDim.x + threadIdx.x;
    if (i < n) {
        float v = src[i];
        dst[i] = v;
        int vv = i / ND, j = i - vv * ND;
        split2h(v, g_cath[(size_t)vv * 256 + 128 + j], g_catl[(size_t)vv * 256 + 128 + j]);
    }
}

__global__ void zero_cnt() {
    int i = blockIdx.x * blockDim.x + threadIdx.x;
    if (i < NN) g_cnt[i] = 0;
}

__global__ void count_kernel(const int* __restrict__ dst) {
    int e = blockIdx.x * blockDim.x + threadIdx.x;
    if (e < NE) atomicAdd(&g_cnt[dst[e]], 1);
}

__global__ void scan1() {
    __shared__ int buf[SCAN_BLK];
    int tid = threadIdx.x;
    int i = blockIdx.x * SCAN_BLK + tid;
    buf[tid] = (i < NN) ? g_cnt[i] : 0;
    __syncthreads();
    #pragma unroll
    for (int off = 1; off < SCAN_BLK; off <<= 1) {
        int t = (tid >= off) ? buf[tid - off] : 0;
        __syncthreads();
        buf[tid] += t;
        __syncthreads();
    }
    if (i < NN) g_rowptr[1 + i] = buf[tid];
    if (tid == SCAN_BLK - 1) g_bsum[blockIdx.x] = buf[tid];
}

__global__ void scan2() {
    __shared__ int buf[64];
    int tid = threadIdx.x;
    int own = (tid < NSCANBLK) ? g_bsum[tid] : 0;
    buf[tid] = own;
    __syncthreads();
    #pragma unroll
    for (int off = 1; off < 64; off <<= 1) {
        int t = (tid >= off) ? buf[tid - off] : 0;
        __syncthreads();
        buf[tid] += t;
        __syncthreads();
    }
    if (tid < NSCANBLK) g_boffs[tid] = buf[tid] - own;
}

__global__ void scan3() {
    int i = blockIdx.x * blockDim.x + threadIdx.x;
    if (i >= NN) return;
    int b = i / SCAN_BLK;
    int incl = g_rowptr[1 + i] + g_boffs[b];
    g_rowptr[1 + i] = incl;
    int c = g_cnt[i];
    g_cursor[i] = incl - c;
    g_degf[i]   = (float)c;
    if (i == 0) g_rowptr[0] = 0;
}

__global__ void fill_kernel(const int* __restrict__ dst) {
    int e = blockIdx.x * blockDim.x + threadIdx.x;
    if (e < NE) {
        int d = dst[e];
        int p = atomicAdd(&g_cursor[d], 1);
        g_eidx[p] = e;
    }
}

// per-node edge-feature sum (once; invariant across rounds)
__global__ void esum_kernel(const float* __restrict__ he) {
    int warp = (blockIdx.x * blockDim.x + threadIdx.x) >> 5;
    int lane = threadIdx.x & 31;
    if (warp >= NN) return;
    int beg = g_rowptr[warp], end = g_rowptr[warp + 1];
    float se = 0.f;
    for (int i = beg; i < end; i++)
        se += he[(size_t)g_eidx[i] * ED + lane];
    g_E[(size_t)warp * ED + lane] = se;
}

// ---------------- merged weight transpose (single fp16, one launch) ----------
// range [0, ND*KPAD)               -> Bmsg
// range [+0, 256*256)              -> Brz (+ g_brz for idx<256)
// range [+0, ND*ND)                -> Bin
// range [+0, ND*ND)                -> Bwn
#define CW_MSG  (ND * KPAD)                 // 36864
#define CW_RZ   (256 * 256)                 // 65536
#define CW_N    (ND * ND)                   // 16384
#define CW_TOTAL (CW_MSG + CW_RZ + 2 * CW_N)

__global__ void conv_all(const float* __restrict__ Wmsg,
                         const float* __restrict__ Wih, const float* __restrict__ Whh,
                         const float* __restrict__ bih, const float* __restrict__ bhh) {
    int idx = blockIdx.x * blockDim.x + threadIdx.x;
    if (idx >= CW_TOTAL) return;
    if (idx < CW_MSG) {
        int n = idx / KPAD;
        int k = idx - n * KPAD;
        g_Bmsg[idx] = __float2half_rn(Wmsg[(size_t)k * ND + n]);
        return;
    }
    idx -= CW_MSG;
    if (idx < CW_RZ) {
        int n = idx >> 8;
        int k = idx & 255;
        float v = (k < 128) ? Wih[(size_t)k * GD + n] : Whh[(size_t)(k - 128) * GD + n];
        g_Brz[idx] = __float2half_rn(v);
        if (idx < 256) g_brz[idx] = bih[idx] + bhh[idx];
        return;
    }
    idx -= CW_RZ;
    if (idx < CW_N) {
        int n = idx >> 7;
        int k = idx & 127;
        g_Bin[idx] = __float2half_rn(Wih[(size_t)k * GD + 256 + n]);
        return;
    }
    idx -= CW_N;
    {
        int n = idx >> 7;
        int k = idx & 127;
        g_Bwn[idx] = __float2half_rn(Whh[(size_t)k * GD + 256 + n]);
    }
}

// ---------------- gather: X = [S | deg*hv | E] as fp16 splits ----------------
// float4 row loads: lane l covers features 4l..4l+3. Per-feature accumulation
// order over edges is IDENTICAL to the scalar version (bit-exact X).
__global__ void gather_kernel(const float* __restrict__ hv, const int* __restrict__ src) {
    int warp = (blockIdx.x * blockDim.x + threadIdx.x) >> 5;
    int lane = threadIdx.x & 31;
    if (warp >= NN) return;
    int v = warp;
    int beg = g_rowptr[v];
    int end = g_rowptr[v + 1];
    float s0 = 0.f, s1 = 0.f, s2 = 0.f, s3 = 0.f;
    const float4* hv4 = (const float4*)hv;
    for (int i = beg; i < end; i++) {
        int e = g_eidx[i];
        int s = src[e];
        float4 r = hv4[(size_t)s * (ND / 4) + lane];
        s0 += r.x; s1 += r.y; s2 += r.z; s3 += r.w;
    }
    float d = g_degf[v];
    float4 hr = hv4[(size_t)v * (ND / 4) + lane];
    __half* xh = g_Xh + (size_t)v * KPAD;
    __half* xl = g_Xl + (size_t)v * KPAD;
    float vals[9];
    vals[0] = s0; vals[1] = s1; vals[2] = s2; vals[3] = s3;
    vals[4] = d * hr.x;
    vals[5] = d * hr.y;
    vals[6] = d * hr.z;
    vals[7] = d * hr.w;
    vals[8] = g_E[(size_t)v * ED + lane];
    #pragma unroll
    for (int q = 0; q < 4; q++)
        split2h(vals[q], xh[4 * lane + q], xl[4 * lane + q]);
    #pragma unroll
    for (int q = 0; q < 4; q++)
        split2h(vals[4 + q], xh[128 + 4 * lane + q], xl[128 + 4 * lane + q]);
    split2h(vals[8], xh[256 + lane], xl[256 + lane]);
}

// ---------------- cp.async 3-stage HMMA fp16 A-split GEMM body ---------------
// C[M, ...] = (Ah+Al)[M,K] @ B^T  (B stored [Ncols][K], K-major fp16)
//   + rowscale*bias.  128x128 CTA tile, 8 warps, K chunk 32, 3 smem stages.
// 2 MMA passes: Ah@B + Al@B, fp32 accumulate.
#define KC 32
#define STG_BYTES 24576   // 3 tiles (Ah, Al, B) x 8KB per stage
#define NSTG 3
#define SMG_BIAS  0
#define SMG_STAGE 1024
#define SMG_TOTAL (1024 + NSTG * STG_BYTES)   // 74752 -> 2 CTAs/SM with L1 headroom

__device__ __forceinline__
void gemm_body(const __half* __restrict__ Ah, const __half* __restrict__ Al,
               int lda,
               const __half* __restrict__ B, int ldb,
               const float* __restrict__ bias, const float* __restrict__ rowscale,
               float* __restrict__ Cf, int ldcf,
               __half* __restrict__ Chi, __half* __restrict__ Clo, int ldch,
               int M, int K, int blockRow, int blockCol, char* smem) {
    int tid = threadIdx.x, wid = tid >> 5, lane = tid & 31;
    int warpRow = (wid >> 2) * 64;   // 0 / 64
    int warpCol = (wid & 3) * 32;    // 0..96

    float* sBias = (float*)(smem + SMG_BIAS);
    if (tid < 128) sBias[tid] = bias[blockCol + tid];

    uint32_t sstage = smem_u32(smem + SMG_STAGE);

    float acc[4][4][4];
    #pragma unroll
    for (int mt = 0; mt < 4; mt++)
        #pragma unroll
        for (int nt = 0; nt < 4; nt++)
            #pragma unroll
            for (int q = 0; q < 4; q++) acc[mt][nt][q] = 0.f;

    // per-thread load mapping: 2 x 16B vecs per tile (128 rows x 64B rows)
    int l0 = tid, l1 = 256 + tid;
    int r0l = l0 >> 2, c0 = (l0 & 3) * 16;
    int r1l = l1 >> 2, c1 = (l1 & 3) * 16;
    int sw0 = (r0l * 64 + c0) ^ (((r0l * 64 + c0) >> 3) & 0x30);
    int sw1 = (r1l * 64 + c1) ^ (((r1l * 64 + c1) >> 3) & 0x30);
    int ga0 = blockRow + r0l; if (ga0 >= M) ga0 = M - 1;
    int ga1 = blockRow + r1l; if (ga1 >= M) ga1 = M - 1;
    int gb0 = blockCol + r0l;
    int gb1 = blockCol + r1l;

    int nchunks = K / KC;

    // prologue: prefetch chunks 0 and 1 (nchunks >= 4 for all our calls)
    #pragma unroll
    for (int p = 0; p < 2; p++) {
        int k0 = p * KC;
        uint32_t st = sstage + p * STG_BYTES;
        cpasync16(st + sw0,          (const char*)(Ah + (size_t)ga0 * lda + k0) + c0);
        cpasync16(st + sw1,          (const char*)(Ah + (size_t)ga1 * lda + k0) + c1);
        cpasync16(st + 8192 + sw0,   (const char*)(Al + (size_t)ga0 * lda + k0) + c0);
        cpasync16(st + 8192 + sw1,   (const char*)(Al + (size_t)ga1 * lda + k0) + c1);
        cpasync16(st + 16384 + sw0,  (const char*)(B + (size_t)gb0 * ldb + k0) + c0);
        cpasync16(st + 16384 + sw1,  (const char*)(B + (size_t)gb1 * ldb + k0) + c1);
        asm volatile("cp.async.commit_group;" ::: "memory");
    }

    int lrow  = lane & 15;
    uint32_t lhalf = (uint32_t)((lane >> 4) * 16);
    uint32_t rm = (uint32_t)(((lrow >> 1) & 3) << 4);

    int stage = 0;
    for (int kc = 0; kc < nchunks; kc++) {
        // wait for chunk kc (newest 1 group may still fly), sync all warps
        asm volatile("cp.async.wait_group 1;" ::: "memory");
        __syncthreads();

        // prefetch chunk kc+2 into stage (kc+2)%3 (safe: sync above guarantees
        // all warps finished computing chunk kc-1, which used this stage)
        if (kc + 2 < nchunks) {
            int k0 = (kc + 2) * KC;
            int s2 = stage + 2; if (s2 >= NSTG) s2 -= NSTG;
            uint32_t st = sstage + s2 * STG_BYTES;
            cpasync16(st + sw0,          (const char*)(Ah + (size_t)ga0 * lda + k0) + c0);
            cpasync16(st + sw1,          (const char*)(Ah + (size_t)ga1 * lda + k0) + c1);
            cpasync16(st + 8192 + sw0,   (const char*)(Al + (size_t)ga0 * lda + k0) + c0);
            cpasync16(st + 8192 + sw1,   (const char*)(Al + (size_t)ga1 * lda + k0) + c1);
            cpasync16(st + 16384 + sw0,  (const char*)(B + (size_t)gb0 * ldb + k0) + c0);
            cpasync16(st + 16384 + sw1,  (const char*)(B + (size_t)gb1 * ldb + k0) + c1);
        }
        asm volatile("cp.async.commit_group;" ::: "memory");

        uint32_t stb = sstage + stage * STG_BYTES;
        uint32_t sAH = stb, sAL = stb + 8192, sB = stb + 16384;

        #pragma unroll
        for (int ks = 0; ks < 2; ks++) {
            uint32_t koff = ((uint32_t)(ks * 32) + lhalf) ^ rm;
            uint32_t bf[4][2];
            #pragma unroll
            for (int ng = 0; ng < 2; ng++) {
                uint32_t ro = (uint32_t)(warpCol + ng * 16 + lrow) * 64 + koff;
                uint32_t t[4];
                ldm_x4(t, sB + ro);
                bf[ng * 2 + 0][0] = t[0]; bf[ng * 2 + 1][0] = t[1];
                bf[ng * 2 + 0][1] = t[2]; bf[ng * 2 + 1][1] = t[3];
            }
            #pragma unroll
            for (int mt = 0; mt < 4; mt++) {
                uint32_t ro = (uint32_t)(warpRow + mt * 16 + lrow) * 64 + koff;
                uint32_t ah[4], al[4];
                ldm_x4(ah, sAH + ro);
                ldm_x4(al, sAL + ro);
                #pragma unroll
                for (int nt = 0; nt < 4; nt++) {
                    mma_f16(acc[mt][nt], ah, bf[nt]);
                    mma_f16(acc[mt][nt], al, bf[nt]);
                }
            }
        }
        stage++; if (stage >= NSTG) stage = 0;
    }

    // ---- epilogue ----
    int rbase = blockRow + warpRow;
    #pragma unroll
    for (int mt = 0; mt < 4; mt++) {
        int r0 = rbase + mt * 16 + (lane >> 2);
        int r1 = r0 + 8;
        float rs0 = 1.f, rs1 = 1.f;
        if (rowscale) {
            if (r0 < M) rs0 = rowscale[r0];
            if (r1 < M) rs1 = rowscale[r1];
        }
        #pragma unroll
        for (int nt = 0; nt < 4; nt++) {
            int col = warpCol + nt * 8 + (lane & 3) * 2;
            float b0 = sBias[col], b1 = sBias[col + 1];
            int gcol = blockCol + col;
            float v00 = acc[mt][nt][0] + rs0 * b0;
            float v01 = acc[mt][nt][1] + rs0 * b1;
            float v10 = acc[mt][nt][2] + rs1 * b0;
            float v11 = acc[mt][nt][3] + rs1 * b1;
            if (Cf) {
                if (r0 < M) *(float2*)(Cf + (size_t)r0 * ldcf + gcol) = make_float2(v00, v01);
                if (r1 < M) *(float2*)(Cf + (size_t)r1 * ldcf + gcol) = make_float2(v10, v11);
            }
            if (Chi) {
                __half h0, l0x, h1, l1;
                if (r0 < M) {
                    split2h(v00, h0, l0x); split2h(v01, h1, l1);
                    *(unsigned*)(Chi + (size_t)r0 * ldch + gcol) =
                        ((unsigned)__half_as_ushort(h1) << 16) | __half_as_ushort(h0);
                    *(unsigned*)(Clo + (size_t)r0 * ldch + gcol) =
                        ((unsigned)__half_as_ushort(l1) << 16) | __half_as_ushort(l0x);
                }
                if (r1 < M) {
                    split2h(v10, h0, l0x); split2h(v11, h1, l1);
                    *(unsigned*)(Chi + (size_t)r1 * ldch + gcol) =
                        ((unsigned)__half_as_ushort(h1) << 16) | __half_as_ushort(h0);
                    *(unsigned*)(Clo + (size_t)r1 * ldch + gcol) =
                        ((unsigned)__half_as_ushort(l1) << 16) | __half_as_ushort(l0x);
                }
            }
        }
    }
}

// msg GEMM: a = X @ Wmsg + deg*b_msg -> cat cols 0-127 (fp16 splits)
__global__ __launch_bounds__(256, 2)
void gemm_msg(const float* __restrict__ bmsg) {
    extern __shared__ char smem[];
    gemm_body(g_Xh, g_Xl, KPAD, g_Bmsg, KPAD,
              bmsg, g_degf,
              (float*)nullptr, 0, g_cath, g_catl, 256,
              NN, KPAD, blockIdx.y * 128, 0, smem);
}

// merged gate GEMMs: x=0,1 -> grz cols; x=2 -> in_ = a@Wih_n; x=3 -> hn = H@Whh_n
__global__ __launch_bounds__(256, 2)
void gemm_gates(const float* __restrict__ bihn, const float* __restrict__ bhhn) {
    extern __shared__ char smem[];
    int bx = blockIdx.x;
    if (bx < 2) {
        gemm_body(g_cath, g_catl, 256, g_Brz, 256,
                  g_brz, (const float*)nullptr,
                  g_grz, 256, (__half*)nullptr, (__half*)nullptr, 0,
                  NN, 256, blockIdx.y * 128, bx * 128, smem);
    } else if (bx == 2) {
        gemm_body(g_cath, g_catl, 256, g_Bin, ND,
                  bihn, (const float*)nullptr,
                  g_in, ND, (__half*)nullptr, (__half*)nullptr, 0,
                  NN, ND, blockIdx.y * 128, 0, smem);
    } else {
        gemm_body(g_cath + 128, g_catl + 128, 256, g_Bwn, ND,
                  bhhn, (const float*)nullptr,
                  g_hn, ND, (__half*)nullptr, (__half*)nullptr, 0,
                  NN, ND, blockIdx.y * 128, 0, smem);
    }
}

// ---------------- GRU elementwise --------------------------------------------
__global__ void gru_kernel(float* __restrict__ hv) {
    int idx = blockIdx.x * blockDim.x + threadIdx.x;
    if (idx >= NN * ND) return;
    int v = idx / ND;
    int j = idx - v * ND;
    float grv = g_grz[(size_t)v * 256 + j];
    float gzv = g_grz[(size_t)v * 256 + 128 + j];
    float inv = g_in[(size_t)v * ND + j];
    float hnv = g_hn[(size_t)v * ND + j];
    float r = 1.0f / (1.0f + expf(-grv));
    float z = 1.0f / (1.0f + expf(-gzv));
    float n = tanhf(inv + r * hnv);
    float h = hv[idx];
    float o = (1.0f - z) * n + z * h;
    hv[idx] = o;
    split2h(o, g_cath[(size_t)v * 256 + 128 + j], g_catl[(size_t)v * 256 + 128 + j]);
}

// ---------------- launch -----------------------------------------------------
extern "C" void kernel_launch(void* const* d_in, const int* in_sizes, int n_in,
                              void* d_out, int out_size) {
    const float* hv    = (const float*)d_in[0];
    const float* he    = (const float*)d_in[1];
    const int*   src   = (const int*)d_in[2];
    const int*   dst   = (const int*)d_in[3];
    const float* W_msg = (const float*)d_in[4];
    const float* b_msg = (const float*)d_in[5];
    const float* W_ih  = (const float*)d_in[6];
    const float* W_hh  = (const float*)d_in[7];
    const float* b_ih  = (const float*)d_in[8];
    const float* b_hh  = (const float*)d_in[9];
    float* H = (float*)d_out;

    static int attr_done = 0;
    if (!attr_done) {
        cudaFuncSetAttribute(gemm_msg,   cudaFuncAttributeMaxDynamicSharedMemorySize, SMG_TOTAL);
        cudaFuncSetAttribute(gemm_gates, cudaFuncAttributeMaxDynamicSharedMemorySize, SMG_TOTAL);
        attr_done = 1;
    }

    copy_split_kernel<<<(NN * ND + 255) / 256, 256>>>(hv, H, NN * ND);
    zero_cnt<<<(NN + 255) / 256, 256>>>();
    count_kernel<<<(NE + 255) / 256, 256>>>(dst);
    scan1<<<NSCANBLK, SCAN_BLK>>>();
    scan2<<<1, 64>>>();
    scan3<<<(NN + 255) / 256, 256>>>();
    fill_kernel<<<(NE + 255) / 256, 256>>>(dst);
    esum_kernel<<<(NN * 32 + 255) / 256, 256>>>(he);

    int mtiles = (NN + 127) / 128;   // 391

    for (int t = 0; t < NROUNDS; t++) {
        conv_all<<<(CW_TOTAL + 255) / 256, 256>>>(W_msg + (size_t)t * CATD * ND,
                                                  W_ih + (size_t)t * ND * GD,
                                                  W_hh + (size_t)t * ND * GD,
                                                  b_ih + (size_t)t * GD,
                                                  b_hh + (size_t)t * GD);

        gather_kernel<<<(NN * 32 + 255) / 256, 256>>>(H, src);

        gemm_msg<<<dim3(1, mtiles), 256, SMG_TOTAL>>>(b_msg + (size_t)t * ND);
        gemm_gates<<<dim3(4, mtiles), 256, SMG_TOTAL>>>(b_ih + (size_t)t * GD + 256,
                                                        b_hh + (size_t)t * GD + 256);

        gru_kernel<<<(NN * ND + 255) / 256, 256>>>(H);
    }
}

// round 15
// speedup vs baseline: 1.0811x; 1.0587x over previous
#include <cuda_runtime.h>
#include <cuda_fp16.h>
#include <math.h>
#include <stdint.h>

// Problem constants
#define NN      50000
#define NE      800000
#define ND      128
#define ED      32
#define CATD    288
#define KPAD    288     // divisible by KC=32
#define GD      384     // 3*ND
#define NROUNDS 2

#define SCAN_BLK 1024
#define NSCANBLK ((NN + SCAN_BLK - 1) / SCAN_BLK)   // 49

// ---------------- device scratch -------------------------------------------
__device__ int   g_cnt[NN];
__device__ int   g_rowptr[NN + 1];
__device__ int   g_cursor[NN];
__device__ float g_degf[NN];
__device__ int   g_bsum[64];
__device__ int   g_boffs[64];
__device__ int   g_eidx[NE];
__device__ float g_E[(size_t)NN * ED];          // per-node edge-feature sum (round-invariant)

__device__ __half g_Xh[(size_t)NN * KPAD];      // A-split hi of X
__device__ __half g_Xl[(size_t)NN * KPAD];      // A-split lo of X
// cat = [a (cols 0-127) | H (cols 128-255)] fp16 hi/lo
__device__ __half g_cath[(size_t)NN * 256];
__device__ __half g_catl[(size_t)NN * 256];
__device__ float g_grz[(size_t)NN * 256];
__device__ float g_in[(size_t)NN * ND];
__device__ float g_hn[(size_t)NN * ND];

// weights (per round, rebuilt) — single fp16 (B-side rounding ~2^-12 only)
__device__ __half g_Bmsg[ND * KPAD];
__device__ __half g_Brz[256 * 256];   // stacked [Wih;Whh] r,z gates, transposed
__device__ __half g_Bin[ND * ND];     // Wih_n transposed
__device__ __half g_Bwn[ND * ND];     // Whh_n transposed
__device__ float g_brz[256];          // b_ih + b_hh (r,z gates)

// ---------------- small helpers --------------------------------------------
__device__ __forceinline__ void split2h(float x, __half& h, __half& l) {
    h = __float2half_rn(x);
    l = __float2half_rn(x - __half2float(h));
}

__device__ __forceinline__ uint32_t smem_u32(const void* p) {
    uint32_t a;
    asm("{ .reg .u64 t; cvta.to.shared.u64 t, %1; cvt.u32.u64 %0, t; }" : "=r"(a) : "l"(p));
    return a;
}

__device__ __forceinline__ void ldm_x4(uint32_t* r, uint32_t addr) {
    asm volatile("ldmatrix.sync.aligned.m8n8.x4.shared.b16 {%0,%1,%2,%3}, [%4];"
        : "=r"(r[0]), "=r"(r[1]), "=r"(r[2]), "=r"(r[3]) : "r"(addr));
}

__device__ __forceinline__ void mma_f16(float* c, const uint32_t* a, const uint32_t* b) {
    asm volatile(
        "mma.sync.aligned.m16n8k16.row.col.f32.f16.f16.f32 "
        "{%0,%1,%2,%3}, {%4,%5,%6,%7}, {%8,%9}, {%0,%1,%2,%3};"
        : "+f"(c[0]), "+f"(c[1]), "+f"(c[2]), "+f"(c[3])
        : "r"(a[0]), "r"(a[1]), "r"(a[2]), "r"(a[3]), "r"(b[0]), "r"(b[1]));
}

__device__ __forceinline__ void cpasync16(uint32_t saddr, const void* gptr) {
    asm volatile("cp.async.cg.shared.global [%0], [%1], 16;"
                 :: "r"(saddr), "l"(gptr));
}

// ---------------- init / CSR kernels ----------------------------------------
__global__ void copy_split_kernel(const float* __restrict__ src, float* __restrict__ dst,
                                  int n) {
    int i = blockIdx.x * blockDim.x + threadIdx.x;
    if (i < n) {
        float v = src[i];
        dst[i] = v;
        int vv = i / ND, j = i - vv * ND;
        split2h(v, g_cath[(size_t)vv * 256 + 128 + j], g_catl[(size_t)vv * 256 + 128 + j]);
    }
}

__global__ void zero_cnt() {
    int i = blockIdx.x * blockDim.x + threadIdx.x;
    if (i < NN) g_cnt[i] = 0;
}

__global__ void count_kernel(const int* __restrict__ dst) {
    int e = blockIdx.x * blockDim.x + threadIdx.x;
    if (e < NE) atomicAdd(&g_cnt[dst[e]], 1);
}

__global__ void scan1() {
    __shared__ int buf[SCAN_BLK];
    int tid = threadIdx.x;
    int i = blockIdx.x * SCAN_BLK + tid;
    buf[tid] = (i < NN) ? g_cnt[i] : 0;
    __syncthreads();
    #pragma unroll
    for (int off = 1; off < SCAN_BLK; off <<= 1) {
        int t = (tid >= off) ? buf[tid - off] : 0;
        __syncthreads();
        buf[tid] += t;
        __syncthreads();
    }
    if (i < NN) g_rowptr[1 + i] = buf[tid];
    if (tid == SCAN_BLK - 1) g_bsum[blockIdx.x] = buf[tid];
}

__global__ void scan2() {
    __shared__ int buf[64];
    int tid = threadIdx.x;
    int own = (tid < NSCANBLK) ? g_bsum[tid] : 0;
    buf[tid] = own;
    __syncthreads();
    #pragma unroll
    for (int off = 1; off < 64; off <<= 1) {
        int t = (tid >= off) ? buf[tid - off] : 0;
        __syncthreads();
        buf[tid] += t;
        __syncthreads();
    }
    if (tid < NSCANBLK) g_boffs[tid] = buf[tid] - own;
}

__global__ void scan3() {
    int i = blockIdx.x * blockDim.x + threadIdx.x;
    if (i >= NN) return;
    int b = i / SCAN_BLK;
    int incl = g_rowptr[1 + i] + g_boffs[b];
    g_rowptr[1 + i] = incl;
    int c = g_cnt[i];
    g_cursor[i] = incl - c;
    g_degf[i]   = (float)c;
    if (i == 0) g_rowptr[0] = 0;
}

__global__ void fill_kernel(const int* __restrict__ dst) {
    int e = blockIdx.x * blockDim.x + threadIdx.x;
    if (e < NE) {
        int d = dst[e];
        int p = atomicAdd(&g_cursor[d], 1);
        g_eidx[p] = e;
    }
}

// per-node edge-feature sum (once; invariant across rounds)
__global__ void esum_kernel(const float* __restrict__ he) {
    int warp = (blockIdx.x * blockDim.x + threadIdx.x) >> 5;
    int lane = threadIdx.x & 31;
    if (warp >= NN) return;
    int beg = g_rowptr[warp], end = g_rowptr[warp + 1];
    float se = 0.f;
    for (int i = beg; i < end; i++)
        se += he[(size_t)g_eidx[i] * ED + lane];
    g_E[(size_t)warp * ED + lane] = se;
}

// ---------------- merged weight transpose (single fp16, one launch) ----------
#define CW_MSG  (ND * KPAD)                 // 36864
#define CW_RZ   (256 * 256)                 // 65536
#define CW_N    (ND * ND)                   // 16384
#define CW_TOTAL (CW_MSG + CW_RZ + 2 * CW_N)

__global__ void conv_all(const float* __restrict__ Wmsg,
                         const float* __restrict__ Wih, const float* __restrict__ Whh,
                         const float* __restrict__ bih, const float* __restrict__ bhh) {
    int idx = blockIdx.x * blockDim.x + threadIdx.x;
    if (idx >= CW_TOTAL) return;
    if (idx < CW_MSG) {
        int n = idx / KPAD;
        int k = idx - n * KPAD;
        g_Bmsg[idx] = __float2half_rn(Wmsg[(size_t)k * ND + n]);
        return;
    }
    idx -= CW_MSG;
    if (idx < CW_RZ) {
        int n = idx >> 8;
        int k = idx & 255;
        float v = (k < 128) ? Wih[(size_t)k * GD + n] : Whh[(size_t)(k - 128) * GD + n];
        g_Brz[idx] = __float2half_rn(v);
        if (idx < 256) g_brz[idx] = bih[idx] + bhh[idx];
        return;
    }
    idx -= CW_RZ;
    if (idx < CW_N) {
        int n = idx >> 7;
        int k = idx & 127;
        g_Bin[idx] = __float2half_rn(Wih[(size_t)k * GD + 256 + n]);
        return;
    }
    idx -= CW_N;
    {
        int n = idx >> 7;
        int k = idx & 127;
        g_Bwn[idx] = __float2half_rn(Whh[(size_t)k * GD + 256 + n]);
    }
}

// ---------------- gather: X = [S | deg*hv | E] as fp16 splits ----------------
// scalar loads (R11 form): 4 outstanding LDG.32 per edge iteration hide L2
// latency better than one LDG.128 on this dependent-index chain.
__global__ void gather_kernel(const float* __restrict__ hv, const int* __restrict__ src) {
    int warp = (blockIdx.x * blockDim.x + threadIdx.x) >> 5;
    int lane = threadIdx.x & 31;
    if (warp >= NN) return;
    int v = warp;
    int beg = g_rowptr[v];
    int end = g_rowptr[v + 1];
    float s0 = 0.f, s1 = 0.f, s2 = 0.f, s3 = 0.f;
    for (int i = beg; i < end; i++) {
        int e = g_eidx[i];
        int s = src[e];
        const float* hr = hv + (size_t)s * ND;
        s0 += hr[lane];
        s1 += hr[32 + lane];
        s2 += hr[64 + lane];
        s3 += hr[96 + lane];
    }
    float d = g_degf[v];
    const float* hvr = hv + (size_t)v * ND;
    __half* xh = g_Xh + (size_t)v * KPAD;
    __half* xl = g_Xl + (size_t)v * KPAD;
    float vals[9];
    vals[0] = s0; vals[1] = s1; vals[2] = s2; vals[3] = s3;
    vals[4] = d * hvr[lane];
    vals[5] = d * hvr[32 + lane];
    vals[6] = d * hvr[64 + lane];
    vals[7] = d * hvr[96 + lane];
    vals[8] = g_E[(size_t)v * ED + lane];
    #pragma unroll
    for (int s = 0; s < 9; s++)
        split2h(vals[s], xh[s * 32 + lane], xl[s * 32 + lane]);
}

// ---------------- cp.async 3-stage HMMA fp16 A-split GEMM body ---------------
// C[M, ...] = (Ah+Al)[M,K] @ B^T  (B stored [Ncols][K], K-major fp16)
//   + rowscale*bias.  128x128 CTA tile, 8 warps in 4x2 layout (32x64 per warp),
//   K chunk 32, 3 smem stages.  2 MMA passes: Ah@B + Al@B, fp32 accumulate.
//   Per-output K-order identical to previous layouts (bit-exact results).
#define KC 32
#define STG_BYTES 24576   // 3 tiles (Ah, Al, B) x 8KB per stage
#define NSTG 3
#define SMG_BIAS  0
#define SMG_STAGE 1024
#define SMG_TOTAL (1024 + NSTG * STG_BYTES)   // 74752 -> 2 CTAs/SM with L1 headroom

__device__ __forceinline__
void gemm_body(const __half* __restrict__ Ah, const __half* __restrict__ Al,
               int lda,
               const __half* __restrict__ B, int ldb,
               const float* __restrict__ bias, const float* __restrict__ rowscale,
               float* __restrict__ Cf, int ldcf,
               __half* __restrict__ Chi, __half* __restrict__ Clo, int ldch,
               int M, int K, int blockRow, int blockCol, char* smem) {
    int tid = threadIdx.x, wid = tid >> 5, lane = tid & 31;
    int warpRow = (wid >> 1) * 32;   // 0,32,64,96
    int warpCol = (wid & 1) * 64;    // 0,64

    float* sBias = (float*)(smem + SMG_BIAS);
    if (tid < 128) sBias[tid] = bias[blockCol + tid];

    uint32_t sstage = smem_u32(smem + SMG_STAGE);

    float acc[2][8][4];
    #pragma unroll
    for (int mt = 0; mt < 2; mt++)
        #pragma unroll
        for (int nt = 0; nt < 8; nt++)
            #pragma unroll
            for (int q = 0; q < 4; q++) acc[mt][nt][q] = 0.f;

    // per-thread load mapping: 2 x 16B vecs per tile (128 rows x 64B rows)
    int l0 = tid, l1 = 256 + tid;
    int r0l = l0 >> 2, c0 = (l0 & 3) * 16;
    int r1l = l1 >> 2, c1 = (l1 & 3) * 16;
    int sw0 = (r0l * 64 + c0) ^ (((r0l * 64 + c0) >> 3) & 0x30);
    int sw1 = (r1l * 64 + c1) ^ (((r1l * 64 + c1) >> 3) & 0x30);
    int ga0 = blockRow + r0l; if (ga0 >= M) ga0 = M - 1;
    int ga1 = blockRow + r1l; if (ga1 >= M) ga1 = M - 1;
    int gb0 = blockCol + r0l;
    int gb1 = blockCol + r1l;

    int nchunks = K / KC;

    // prologue: prefetch chunks 0 and 1 (nchunks >= 4 for all our calls)
    #pragma unroll
    for (int p = 0; p < 2; p++) {
        int k0 = p * KC;
        uint32_t st = sstage + p * STG_BYTES;
        cpasync16(st + sw0,          (const char*)(Ah + (size_t)ga0 * lda + k0) + c0);
        cpasync16(st + sw1,          (const char*)(Ah + (size_t)ga1 * lda + k0) + c1);
        cpasync16(st + 8192 + sw0,   (const char*)(Al + (size_t)ga0 * lda + k0) + c0);
        cpasync16(st + 8192 + sw1,   (const char*)(Al + (size_t)ga1 * lda + k0) + c1);
        cpasync16(st + 16384 + sw0,  (const char*)(B + (size_t)gb0 * ldb + k0) + c0);
        cpasync16(st + 16384 + sw1,  (const char*)(B + (size_t)gb1 * ldb + k0) + c1);
        asm volatile("cp.async.commit_group;" ::: "memory");
    }

    int lrow  = lane & 15;
    uint32_t lhalf = (uint32_t)((lane >> 4) * 16);
    uint32_t rm = (uint32_t)(((lrow >> 1) & 3) << 4);

    int stage = 0;
    for (int kc = 0; kc < nchunks; kc++) {
        asm volatile("cp.async.wait_group 1;" ::: "memory");
        __syncthreads();

        if (kc + 2 < nchunks) {
            int k0 = (kc + 2) * KC;
            int s2 = stage + 2; if (s2 >= NSTG) s2 -= NSTG;
            uint32_t st = sstage + s2 * STG_BYTES;
            cpasync16(st + sw0,          (const char*)(Ah + (size_t)ga0 * lda + k0) + c0);
            cpasync16(st + sw1,          (const char*)(Ah + (size_t)ga1 * lda + k0) + c1);
            cpasync16(st + 8192 + sw0,   (const char*)(Al + (size_t)ga0 * lda + k0) + c0);
            cpasync16(st + 8192 + sw1,   (const char*)(Al + (size_t)ga1 * lda + k0) + c1);
            cpasync16(st + 16384 + sw0,  (const char*)(B + (size_t)gb0 * ldb + k0) + c0);
            cpasync16(st + 16384 + sw1,  (const char*)(B + (size_t)gb1 * ldb + k0) + c1);
        }
        asm volatile("cp.async.commit_group;" ::: "memory");

        uint32_t stb = sstage + stage * STG_BYTES;
        uint32_t sAH = stb, sAL = stb + 8192, sB = stb + 16384;

        #pragma unroll
        for (int ks = 0; ks < 2; ks++) {
            uint32_t koff = ((uint32_t)(ks * 32) + lhalf) ^ rm;
            uint32_t bf[8][2];
            #pragma unroll
            for (int ng = 0; ng < 4; ng++) {
                uint32_t ro = (uint32_t)(warpCol + ng * 16 + lrow) * 64 + koff;
                uint32_t t[4];
                ldm_x4(t, sB + ro);
                bf[ng * 2 + 0][0] = t[0]; bf[ng * 2 + 1][0] = t[1];
                bf[ng * 2 + 0][1] = t[2]; bf[ng * 2 + 1][1] = t[3];
            }
            #pragma unroll
            for (int mt = 0; mt < 2; mt++) {
                uint32_t ro = (uint32_t)(warpRow + mt * 16 + lrow) * 64 + koff;
                uint32_t ah[4], al[4];
                ldm_x4(ah, sAH + ro);
                ldm_x4(al, sAL + ro);
                #pragma unroll
                for (int nt = 0; nt < 8; nt++) {
                    mma_f16(acc[mt][nt], ah, bf[nt]);
                    mma_f16(acc[mt][nt], al, bf[nt]);
                }
            }
        }
        stage++; if (stage >= NSTG) stage = 0;
    }

    // ---- epilogue ----
    int rbase = blockRow + warpRow;
    #pragma unroll
    for (int mt = 0; mt < 2; mt++) {
        int r0 = rbase + mt * 16 + (lane >> 2);
        int r1 = r0 + 8;
        float rs0 = 1.f, rs1 = 1.f;
        if (rowscale) {
            if (r0 < M) rs0 = rowscale[r0];
            if (r1 < M) rs1 = rowscale[r1];
        }
        #pragma unroll
        for (int nt = 0; nt < 8; nt++) {
            int col = warpCol + nt * 8 + (lane & 3) * 2;
            float b0 = sBias[col], b1 = sBias[col + 1];
            int gcol = blockCol + col;
            float v00 = acc[mt][nt][0] + rs0 * b0;
            float v01 = acc[mt][nt][1] + rs0 * b1;
            float v10 = acc[mt][nt][2] + rs1 * b0;
            float v11 = acc[mt][nt][3] + rs1 * b1;
            if (Cf) {
                if (r0 < M) *(float2*)(Cf + (size_t)r0 * ldcf + gcol) = make_float2(v00, v01);
                if (r1 < M) *(float2*)(Cf + (size_t)r1 * ldcf + gcol) = make_float2(v10, v11);
            }
            if (Chi) {
                __half h0, l0x, h1, l1;
                if (r0 < M) {
                    split2h(v00, h0, l0x); split2h(v01, h1, l1);
                    *(unsigned*)(Chi + (size_t)r0 * ldch + gcol) =
                        ((unsigned)__half_as_ushort(h1) << 16) | __half_as_ushort(h0);
                    *(unsigned*)(Clo + (size_t)r0 * ldch + gcol) =
                        ((unsigned)__half_as_ushort(l1) << 16) | __half_as_ushort(l0x);
                }
                if (r1 < M) {
                    split2h(v10, h0, l0x); split2h(v11, h1, l1);
                    *(unsigned*)(Chi + (size_t)r1 * ldch + gcol) =
                        ((unsigned)__half_as_ushort(h1) << 16) | __half_as_ushort(h0);
                    *(unsigned*)(Clo + (size_t)r1 * ldch + gcol) =
                        ((unsigned)__half_as_ushort(l1) << 16) | __half_as_ushort(l0x);
                }
            }
        }
    }
}

// msg GEMM: a = X @ Wmsg + deg*b_msg -> cat cols 0-127 (fp16 splits)
__global__ __launch_bounds__(256, 2)
void gemm_msg(const float* __restrict__ bmsg) {
    extern __shared__ char smem[];
    gemm_body(g_Xh, g_Xl, KPAD, g_Bmsg, KPAD,
              bmsg, g_degf,
              (float*)nullptr, 0, g_cath, g_catl, 256,
              NN, KPAD, blockIdx.y * 128, 0, smem);
}

// merged gate GEMMs: x=0,1 -> grz cols; x=2 -> in_ = a@Wih_n; x=3 -> hn = H@Whh_n
__global__ __launch_bounds__(256, 2)
void gemm_gates(const float* __restrict__ bihn, const float* __restrict__ bhhn) {
    extern __shared__ char smem[];
    int bx = blockIdx.x;
    if (bx < 2) {
        gemm_body(g_cath, g_catl, 256, g_Brz, 256,
                  g_brz, (const float*)nullptr,
                  g_grz, 256, (__half*)nullptr, (__half*)nullptr, 0,
                  NN, 256, blockIdx.y * 128, bx * 128, smem);
    } else if (bx == 2) {
        gemm_body(g_cath, g_catl, 256, g_Bin, ND,
                  bihn, (const float*)nullptr,
                  g_in, ND, (__half*)nullptr, (__half*)nullptr, 0,
                  NN, ND, blockIdx.y * 128, 0, smem);
    } else {
        gemm_body(g_cath + 128, g_catl + 128, 256, g_Bwn, ND,
                  bhhn, (const float*)nullptr,
                  g_hn, ND, (__half*)nullptr, (__half*)nullptr, 0,
                  NN, ND, blockIdx.y * 128, 0, smem);
    }
}

// ---------------- GRU elementwise --------------------------------------------
__global__ void gru_kernel(float* __restrict__ hv) {
    int idx = blockIdx.x * blockDim.x + threadIdx.x;
    if (idx >= NN * ND) return;
    int v = idx / ND;
    int j = idx - v * ND;
    float grv = g_grz[(size_t)v * 256 + j];
    float gzv = g_grz[(size_t)v * 256 + 128 + j];
    float inv = g_in[(size_t)v * ND + j];
    float hnv = g_hn[(size_t)v * ND + j];
    float r = 1.0f / (1.0f + expf(-grv));
    float z = 1.0f / (1.0f + expf(-gzv));
    float n = tanhf(inv + r * hnv);
    float h = hv[idx];
    float o = (1.0f - z) * n + z * h;
    hv[idx] = o;
    split2h(o, g_cath[(size_t)v * 256 + 128 + j], g_catl[(size_t)v * 256 + 128 + j]);
}

// ---------------- launch -----------------------------------------------------
extern "C" void kernel_launch(void* const* d_in, const int* in_sizes, int n_in,
                              void* d_out, int out_size) {
    const float* hv    = (const float*)d_in[0];
    const float* he    = (const float*)d_in[1];
    const int*   src   = (const int*)d_in[2];
    const int*   dst   = (const int*)d_in[3];
    const float* W_msg = (const float*)d_in[4];
    const float* b_msg = (const float*)d_in[5];
    const float* W_ih  = (const float*)d_in[6];
    const float* W_hh  = (const float*)d_in[7];
    const float* b_ih  = (const float*)d_in[8];
    const float* b_hh  = (const float*)d_in[9];
    float* H = (float*)d_out;

    static int attr_done = 0;
    if (!attr_done) {
        cudaFuncSetAttribute(gemm_msg,   cudaFuncAttributeMaxDynamicSharedMemorySize, SMG_TOTAL);
        cudaFuncSetAttribute(gemm_gates, cudaFuncAttributeMaxDynamicSharedMemorySize, SMG_TOTAL);
        attr_done = 1;
    }

    copy_split_kernel<<<(NN * ND + 255) / 256, 256>>>(hv, H, NN * ND);
    zero_cnt<<<(NN + 255) / 256, 256>>>();
    count_kernel<<<(NE + 255) / 256, 256>>>(dst);
    scan1<<<NSCANBLK, SCAN_BLK>>>();
    scan2<<<1, 64>>>();
    scan3<<<(NN + 255) / 256, 256>>>();
    fill_kernel<<<(NE + 255) / 256, 256>>>(dst);
    esum_kernel<<<(NN * 32 + 255) / 256, 256>>>(he);

    int mtiles = (NN + 127) / 128;   // 391

    for (int t = 0; t < NROUNDS; t++) {
        conv_all<<<(CW_TOTAL + 255) / 256, 256>>>(W_msg + (size_t)t * CATD * ND,
                                                  W_ih + (size_t)t * ND * GD,
                                                  W_hh + (size_t)t * ND * GD,
                                                  b_ih + (size_t)t * GD,
                                                  b_hh + (size_t)t * GD);

        gather_kernel<<<(NN * 32 + 255) / 256, 256>>>(H, src);

        gemm_msg<<<dim3(1, mtiles), 256, SMG_TOTAL>>>(b_msg + (size_t)t * ND);
        gemm_gates<<<dim3(4, mtiles), 256, SMG_TOTAL>>>(b_ih + (size_t)t * GD + 256,
                                                        b_hh + (size_t)t * GD + 256);

        gru_kernel<<<(NN * ND + 255) / 256, 256>>>(H);
    }
}